// round 15
// baseline (speedup 1.0000x reference)
#include <cuda_runtime.h>
#include <cuda_bf16.h>
#include <cuda_fp16.h>
#include <math.h>

#define NN    50000
#define EDG   800000
#define K1    3
#define INC   128
#define NF    64
#define CCH   128   // 2*NF
#define LABEL 10
#define TOTE  (K1*EDG)

#define NTILE     782            // ceil(NN/64)
#define GEMM0BLK  (NTILE*6)      // 4692
#define FUSEGRID  (GEMM0BLK*5)   // 23460: bx%5==0 -> gemm, else scatter
#define HISTBLK   ((TOTE+255)/256)
#define W0E       (K1*INC*NF)    // 24576
#define W12E      (K1*NF*NF)     // 12288
#define TOTW      (W0E + 2*W12E) // 49152
#define WOFF1     W0E
#define WOFF2     (W0E + W12E)

#define PACKH2(d, lo, hi) \
    asm("cvt.rn.f16x2.f32 %0, %1, %2;" : "=r"(d) : "f"(hi), "f"(lo))
#define PACKB2(d, lo, hi) \
    asm("cvt.rn.bf16x2.f32 %0, %1, %2;" : "=r"(d) : "f"(hi), "f"(lo))

// ---------------- scratch (device globals; no allocs allowed) ----------------
// A layout per (k,node): 16 groups of 16B; group g = (r_{4g..4g+3}, i_{4g..4g+3}) fp16
__device__ __half g_A[(size_t)K1 * NN * CCH];
__device__ float g_Hr[NN * NF];
__device__ float g_Hi[NN * NF];
__device__ int   g_cnt[NN + 1];               // zero-init at load; re-zeroed by scatter part
__device__ int   g_off[NN + 1];
__device__ int   g_cursor[NN];
__device__ int2  g_epay[TOTE];                // (k*NN+c, half2(vr,vi))
__device__ __nv_bfloat16 g_WH[TOTW];          // pre-split weights (hi), L0|L1|L2
__device__ __nv_bfloat16 g_WL[TOTW];          // pre-split weights (lo)
__device__ float g_cmean[CCH];
__device__ float g_ca[CCH];
__device__ float g_smean[NN];
__device__ float g_smax[NN];

// ---------------- tensor-core helpers (bf16) ----------------------------------
__device__ __forceinline__ void ldsm_x4(unsigned* r, unsigned addr) {
    asm volatile("ldmatrix.sync.aligned.m8n8.x4.shared.b16 {%0,%1,%2,%3}, [%4];"
                 : "=r"(r[0]), "=r"(r[1]), "=r"(r[2]), "=r"(r[3]) : "r"(addr));
}
__device__ __forceinline__ void ldsm_x4_t(unsigned* r, unsigned addr) {
    asm volatile("ldmatrix.sync.aligned.m8n8.x4.trans.shared.b16 {%0,%1,%2,%3}, [%4];"
                 : "=r"(r[0]), "=r"(r[1]), "=r"(r[2]), "=r"(r[3]) : "r"(addr));
}
__device__ __forceinline__ void mma_bf16(float* c, const unsigned* a, const unsigned* b) {
    asm volatile(
        "mma.sync.aligned.m16n8k16.row.col.f32.bf16.bf16.f32 "
        "{%0,%1,%2,%3}, {%4,%5,%6,%7}, {%8,%9}, {%0,%1,%2,%3};"
        : "+f"(c[0]), "+f"(c[1]), "+f"(c[2]), "+f"(c[3])
        : "r"(a[0]), "r"(a[1]), "r"(a[2]), "r"(a[3]), "r"(b[0]), "r"(b[1]));
}

// split fp32 -> (hi, lo) bf16 pairs, packed 2-wide (bf16: residuals never subnormal)
__device__ __forceinline__ void split2b(float x, float y, unsigned& h, unsigned& l) {
    PACKB2(h, x, y);
    __nv_bfloat162 hh = *(__nv_bfloat162*)&h;
    float2 f = __bfloat1622float2(hh);
    PACKB2(l, x - f.x, y - f.y);
}

// ---------------- GEMM body (tensor, split-bf16): A[k,ri] = H(ri) @ W[k] -----
// 4 warps per tile, M-tile = 64 rows, N = 64, K chunked at 64.
// W comes pre-split from g_WH/g_WL (bit-identical to in-kernel split).
template<int FIN, bool FROMG>
__device__ __forceinline__ void gemm_body(
    int tile, int z,
    const float* __restrict__ HrIn, const float* __restrict__ HiIn,
    const __nv_bfloat16* __restrict__ WHb, const __nv_bfloat16* __restrict__ WLb,
    int tid)
{
    constexpr int S = 72;
    __shared__ __nv_bfloat16 HsH[64 * S], HsL[64 * S];
    __shared__ __nv_bfloat16 WsH[64 * S], WsL[64 * S];

    const int k  = z >> 1, ri = z & 1;
    const float* H;
    if (FROMG) H = ri ? g_Hi : g_Hr;
    else       H = ri ? HiIn : HrIn;
    const __nv_bfloat16* WHg = WHb + k * FIN * NF;
    const __nv_bfloat16* WLg = WLb + k * FIN * NF;
    char* OutB = (char*)g_A + (size_t)k * NN * 256;

    const int row0 = tile * 64;
    const int wid  = tid >> 5;
    const int l    = tid & 31;
    const int m0   = wid * 16;

    float acc[8][4];
    #pragma unroll
    for (int t = 0; t < 8; t++)
        #pragma unroll
        for (int j = 0; j < 4; j++) acc[t][j] = 0.f;

    unsigned hbH = (unsigned)__cvta_generic_to_shared(HsH);
    unsigned hbL = (unsigned)__cvta_generic_to_shared(HsL);
    unsigned wbH = (unsigned)__cvta_generic_to_shared(WsH);
    unsigned wbL = (unsigned)__cvta_generic_to_shared(WsL);

    #pragma unroll
    for (int kc = 0; kc < FIN; kc += 64) {
        if (kc) __syncthreads();
        // H tile [64 x 64] fp32 -> hi/lo bf16
        for (int f = tid; f < 64 * 16; f += 128) {
            int row = f >> 4;
            int c4  = f & 15;
            int gr  = row0 + row;
            float4 v = (gr < NN) ? *(const float4*)&H[(size_t)gr * FIN + kc + c4 * 4]
                                 : make_float4(0.f, 0.f, 0.f, 0.f);
            unsigned h01, l01, h23, l23;
            split2b(v.x, v.y, h01, l01);
            split2b(v.z, v.w, h23, l23);
            *(uint2*)&HsH[row * S + c4 * 4] = make_uint2(h01, h23);
            *(uint2*)&HsL[row * S + c4 * 4] = make_uint2(l01, l23);
        }
        // W tile [64 x 64]: direct copy of pre-split hi/lo
        for (int f = tid; f < 64 * 16; f += 128) {
            int row = f >> 4;
            int c4  = f & 15;
            *(uint2*)&WsH[row * S + c4 * 4] = *(const uint2*)&WHg[(kc + row) * NF + c4 * 4];
            *(uint2*)&WsL[row * S + c4 * 4] = *(const uint2*)&WLg[(kc + row) * NF + c4 * 4];
        }
        __syncthreads();

        #pragma unroll
        for (int kk = 0; kk < 64; kk += 16) {
            unsigned aoff = ((m0 + (l & 15)) * S + kk + (l >> 4) * 8) * 2;
            unsigned aH[4], aL[4];
            ldsm_x4(aH, hbH + aoff);
            ldsm_x4(aL, hbL + aoff);
            #pragma unroll
            for (int t = 0; t < 4; t++) {
                unsigned boff =
                    ((kk + (l & 7) + ((l >> 3) & 1) * 8) * S + t * 16 + (l >> 4) * 8) * 2;
                unsigned bH[4], bL[4];
                ldsm_x4_t(bH, wbH + boff);
                ldsm_x4_t(bL, wbL + boff);
                mma_bf16(acc[2 * t],     aH, bH);
                mma_bf16(acc[2 * t],     aH, bL);
                mma_bf16(acc[2 * t],     aL, bH);
                mma_bf16(acc[2 * t + 1], aH, bH + 2);
                mma_bf16(acc[2 * t + 1], aH, bL + 2);
                mma_bf16(acc[2 * t + 1], aL, bH + 2);
            }
        }
    }

    // epilogue: channel c at byte 16*(c>>2) + ri*8 + (c&3)*2 (gather contract)
    const int q   = l & 3;
    const int gr0 = row0 + m0 + (l >> 2);
    const int gr1 = gr0 + 8;
    #pragma unroll
    for (int t = 0; t < 8; t++) {
        unsigned p01, p23;
        PACKH2(p01, acc[t][0], acc[t][1]);
        PACKH2(p23, acc[t][2], acc[t][3]);
        int col = t * 8 + q * 2;
        int off = 16 * (col >> 2) + ri * 8 + (col & 3) * 2;
        if (gr0 < NN) *(unsigned*)(OutB + (size_t)gr0 * 256 + off) = p01;
        if (gr1 < NN) *(unsigned*)(OutB + (size_t)gr1 * 256 + off) = p23;
    }
}

// ---------------- scatter body (CSR payload placement) ------------------------
__device__ __forceinline__ void scatter_body(
    int e, const int* __restrict__ rows, const int* __restrict__ cols,
    const float* __restrict__ vr, const float* __restrict__ vi)
{
    if (e <= NN) g_cnt[e] = 0;            // re-zero for next graph replay
    if (e >= TOTE) return;
    int k = (e >= 2 * EDG) ? 2 : (e >= EDG) ? 1 : 0;
    int r = rows[e];
    int pos = atomicAdd(&g_cursor[r], 1);
    __half2 hv = __floats2half2_rn(vr[e], vi[e]);
    int2 pay;
    pay.x = k * NN + cols[e];
    pay.y = *(int*)&hv;
    g_epay[pos] = pay;
}

// ---------------- fused: layer-0 GEMM (interleaved) + scatter -----------------
__global__ void __launch_bounds__(128, 4)
gemm0_scatter_k(const float* __restrict__ Xr, const float* __restrict__ Xi,
                const int* __restrict__ rows, const int* __restrict__ cols,
                const float* __restrict__ vr, const float* __restrict__ vi)
{
    int bx = blockIdx.x;
    if (bx % 5 == 0) {
        int g = bx / 5;                       // 0..4691
        gemm_body<INC, false>(g % NTILE, g / NTILE, Xr, Xi, g_WH, g_WL, threadIdx.x);
    } else {
        int sb = (bx / 5) * 4 + (bx % 5 - 1); // 0..18767
        int e  = sb * 128 + threadIdx.x;
        scatter_body(e, rows, cols, vr, vi);
    }
}

// ---------------- GEMM layers 1-2 (pre-split W) -------------------------------
template<int FIN, bool FROMG>
__global__ void __launch_bounds__(128, 4)
gemm_t(const float* __restrict__ HrIn, const float* __restrict__ HiIn, int woff) {
    gemm_body<FIN, FROMG>(blockIdx.x, blockIdx.y, HrIn, HiIn,
                          g_WH + woff, g_WL + woff, threadIdx.x);
}

// ---------------- hist + W pre-split (fused) ----------------------------------
__global__ void histws_k(const int* __restrict__ rows,
                         const float* __restrict__ w0,
                         const float* __restrict__ w1,
                         const float* __restrict__ w2) {
    int bx = blockIdx.x;
    if (bx < HISTBLK) {
        int e = bx * 256 + threadIdx.x;
        if (e < TOTE) atomicAdd(&g_cnt[rows[e]], 1);
    } else {
        int idx = (bx - HISTBLK) * 256 + threadIdx.x;
        if (idx < TOTW) {
            float v;
            if (idx < W0E)        v = w0[idx];
            else if (idx < WOFF2) v = w1[idx - WOFF1];
            else                  v = w2[idx - WOFF2];
            __nv_bfloat16 h = __float2bfloat16(v);
            g_WH[idx] = h;
            g_WL[idx] = __float2bfloat16(v - __bfloat162float(h));
        }
    }
}

// one-block exclusive scan: 1024 threads x 49-element chunks
__global__ void scan_k() {
    const int CHUNK = 49;                 // 1024*49 = 50176 >= NN+1
    __shared__ int sm[1024];
    int t = threadIdx.x;
    int base = t * CHUNK;
    int sum = 0;
    #pragma unroll
    for (int i = 0; i < CHUNK; i++) {
        int idx = base + i;
        if (idx < NN) sum += g_cnt[idx];
    }
    sm[t] = sum;
    __syncthreads();
    #pragma unroll
    for (int d = 1; d < 1024; d <<= 1) {
        int v = (t >= d) ? sm[t - d] : 0;
        __syncthreads();
        sm[t] += v;
        __syncthreads();
    }
    int run = (t == 0) ? 0 : sm[t - 1];
    #pragma unroll
    for (int i = 0; i < CHUNK; i++) {
        int idx = base + i;
        if (idx < NN) {
            g_off[idx]    = run;
            g_cursor[idx] = run;
            run += g_cnt[idx];
        } else if (idx == NN) {
            g_off[NN] = run;
        }
    }
}

// ---------------- SpMM gather: half-warp per edge, high-MLP main loop --------
__global__ void spmm_gather_k(const float* __restrict__ bias) {
    int w    = (blockIdx.x * 256 + threadIdx.x) >> 5;
    int lane = threadIdx.x & 31;
    if (w >= NN) return;
    int half_id = lane >> 4;
    int l16     = lane & 15;

    float aR0=0.f, aR1=0.f, aR2=0.f, aR3=0.f;
    float aI0=0.f, aI1=0.f, aI2=0.f, aI3=0.f;

    const char* Ab = (const char*)g_A + l16 * 16;
    int beg = g_off[w], end = g_off[w + 1];
    int e = beg;

    for (; e + 8 <= end; e += 8) {
        int b4 = e + half_id * 4;
        int2 p0 = g_epay[b4 + 0];
        int2 p1 = g_epay[b4 + 1];
        int2 p2 = g_epay[b4 + 2];
        int2 p3 = g_epay[b4 + 3];
        uint4 q0 = *(const uint4*)(Ab + (((unsigned)p0.x) << 8));
        uint4 q1 = *(const uint4*)(Ab + (((unsigned)p1.x) << 8));
        uint4 q2 = *(const uint4*)(Ab + (((unsigned)p2.x) << 8));
        uint4 q3 = *(const uint4*)(Ab + (((unsigned)p3.x) << 8));
        {
            float2 vv = __half22float2(*(const __half2*)&p0.y);
            float2 r01 = __half22float2(*(const __half2*)&q0.x);
            float2 r23 = __half22float2(*(const __half2*)&q0.y);
            float2 i01 = __half22float2(*(const __half2*)&q0.z);
            float2 i23 = __half22float2(*(const __half2*)&q0.w);
            float a = vv.x, b = vv.y;
            aR0 = fmaf(a, r01.x, fmaf(-b, i01.x, aR0));
            aI0 = fmaf(b, r01.x, fmaf( a, i01.x, aI0));
            aR1 = fmaf(a, r01.y, fmaf(-b, i01.y, aR1));
            aI1 = fmaf(b, r01.y, fmaf( a, i01.y, aI1));
            aR2 = fmaf(a, r23.x, fmaf(-b, i23.x, aR2));
            aI2 = fmaf(b, r23.x, fmaf( a, i23.x, aI2));
            aR3 = fmaf(a, r23.y, fmaf(-b, i23.y, aR3));
            aI3 = fmaf(b, r23.y, fmaf( a, i23.y, aI3));
        }
        {
            float2 vv = __half22float2(*(const __half2*)&p1.y);
            float2 r01 = __half22float2(*(const __half2*)&q1.x);
            float2 r23 = __half22float2(*(const __half2*)&q1.y);
            float2 i01 = __half22float2(*(const __half2*)&q1.z);
            float2 i23 = __half22float2(*(const __half2*)&q1.w);
            float a = vv.x, b = vv.y;
            aR0 = fmaf(a, r01.x, fmaf(-b, i01.x, aR0));
            aI0 = fmaf(b, r01.x, fmaf( a, i01.x, aI0));
            aR1 = fmaf(a, r01.y, fmaf(-b, i01.y, aR1));
            aI1 = fmaf(b, r01.y, fmaf( a, i01.y, aI1));
            aR2 = fmaf(a, r23.x, fmaf(-b, i23.x, aR2));
            aI2 = fmaf(b, r23.x, fmaf( a, i23.x, aI2));
            aR3 = fmaf(a, r23.y, fmaf(-b, i23.y, aR3));
            aI3 = fmaf(b, r23.y, fmaf( a, i23.y, aI3));
        }
        {
            float2 vv = __half22float2(*(const __half2*)&p2.y);
            float2 r01 = __half22float2(*(const __half2*)&q2.x);
            float2 r23 = __half22float2(*(const __half2*)&q2.y);
            float2 i01 = __half22float2(*(const __half2*)&q2.z);
            float2 i23 = __half22float2(*(const __half2*)&q2.w);
            float a = vv.x, b = vv.y;
            aR0 = fmaf(a, r01.x, fmaf(-b, i01.x, aR0));
            aI0 = fmaf(b, r01.x, fmaf( a, i01.x, aI0));
            aR1 = fmaf(a, r01.y, fmaf(-b, i01.y, aR1));
            aI1 = fmaf(b, r01.y, fmaf( a, i01.y, aI1));
            aR2 = fmaf(a, r23.x, fmaf(-b, i23.x, aR2));
            aI2 = fmaf(b, r23.x, fmaf( a, i23.x, aI2));
            aR3 = fmaf(a, r23.y, fmaf(-b, i23.y, aR3));
            aI3 = fmaf(b, r23.y, fmaf( a, i23.y, aI3));
        }
        {
            float2 vv = __half22float2(*(const __half2*)&p3.y);
            float2 r01 = __half22float2(*(const __half2*)&q3.x);
            float2 r23 = __half22float2(*(const __half2*)&q3.y);
            float2 i01 = __half22float2(*(const __half2*)&q3.z);
            float2 i23 = __half22float2(*(const __half2*)&q3.w);
            float a = vv.x, b = vv.y;
            aR0 = fmaf(a, r01.x, fmaf(-b, i01.x, aR0));
            aI0 = fmaf(b, r01.x, fmaf( a, i01.x, aI0));
            aR1 = fmaf(a, r01.y, fmaf(-b, i01.y, aR1));
            aI1 = fmaf(b, r01.y, fmaf( a, i01.y, aI1));
            aR2 = fmaf(a, r23.x, fmaf(-b, i23.x, aR2));
            aI2 = fmaf(b, r23.x, fmaf( a, i23.x, aI2));
            aR3 = fmaf(a, r23.y, fmaf(-b, i23.y, aR3));
            aI3 = fmaf(b, r23.y, fmaf( a, i23.y, aI3));
        }
    }
    for (; e < end; e += 2) {
        int ee = e + half_id;
        int ec = min(ee, end - 1);
        int2 p = g_epay[ec];
        float2 vv = __half22float2(*(const __half2*)&p.y);
        float a = (ee < end) ? vv.x : 0.f;
        float b = (ee < end) ? vv.y : 0.f;
        uint4 q = *(const uint4*)(Ab + (((unsigned)p.x) << 8));
        float2 r01 = __half22float2(*(const __half2*)&q.x);
        float2 r23 = __half22float2(*(const __half2*)&q.y);
        float2 i01 = __half22float2(*(const __half2*)&q.z);
        float2 i23 = __half22float2(*(const __half2*)&q.w);
        aR0 = fmaf(a, r01.x, fmaf(-b, i01.x, aR0));
        aI0 = fmaf(b, r01.x, fmaf( a, i01.x, aI0));
        aR1 = fmaf(a, r01.y, fmaf(-b, i01.y, aR1));
        aI1 = fmaf(b, r01.y, fmaf( a, i01.y, aI1));
        aR2 = fmaf(a, r23.x, fmaf(-b, i23.x, aR2));
        aI2 = fmaf(b, r23.x, fmaf( a, i23.x, aI2));
        aR3 = fmaf(a, r23.y, fmaf(-b, i23.y, aR3));
        aI3 = fmaf(b, r23.y, fmaf( a, i23.y, aI3));
    }

    aR0 += __shfl_xor_sync(0xffffffffu, aR0, 16);
    aR1 += __shfl_xor_sync(0xffffffffu, aR1, 16);
    aR2 += __shfl_xor_sync(0xffffffffu, aR2, 16);
    aR3 += __shfl_xor_sync(0xffffffffu, aR3, 16);
    aI0 += __shfl_xor_sync(0xffffffffu, aI0, 16);
    aI1 += __shfl_xor_sync(0xffffffffu, aI1, 16);
    aI2 += __shfl_xor_sync(0xffffffffu, aI2, 16);
    aI3 += __shfl_xor_sync(0xffffffffu, aI3, 16);

    if (half_id == 0) {
        float4 bv = *(const float4*)&bias[l16 * 4];
        float r0 = aR0 + bv.x, r1 = aR1 + bv.y, r2 = aR2 + bv.z, r3 = aR3 + bv.w;
        float i0 = aI0 + bv.x, i1 = aI1 + bv.y, i2 = aI2 + bv.z, i3 = aI3 + bv.w;
        float4 hr, hi;
        hr.x = (r0 >= 0.f) ? r0 : 0.f;  hi.x = (r0 >= 0.f) ? i0 : 0.f;
        hr.y = (r1 >= 0.f) ? r1 : 0.f;  hi.y = (r1 >= 0.f) ? i1 : 0.f;
        hr.z = (r2 >= 0.f) ? r2 : 0.f;  hi.z = (r2 >= 0.f) ? i2 : 0.f;
        hr.w = (r3 >= 0.f) ? r3 : 0.f;  hi.w = (r3 >= 0.f) ? i3 : 0.f;
        *(float4*)&g_Hr[w * NF + l16 * 4] = hr;
        *(float4*)&g_Hi[w * NF + l16 * 4] = hi;
    }
}

// ---------------- CBAM channel attention -------------------------------------
__global__ void zero_cmean_k() {
    if (threadIdx.x < CCH) g_cmean[threadIdx.x] = 0.f;
}

__global__ void chan_sum_k() {
    const int NPB = 512;
    int t = threadIdx.x;
    int c = t & 127;
    int half = t >> 7;
    int n0 = blockIdx.x * NPB;
    int n1 = min(n0 + NPB, NN);
    const float* src = (c < NF) ? g_Hr : g_Hi;
    int cc = c & (NF - 1);
    float s = 0.f;
    for (int n = n0 + half; n < n1; n += 2) s += src[n * NF + cc];
    __shared__ float sm[256];
    sm[t] = s;
    __syncthreads();
    if (t < 128) atomicAdd(&g_cmean[c], sm[t] + sm[t + 128]);
}

__global__ void ca_k(const float* __restrict__ w1, const float* __restrict__ w2) {
    __shared__ float avg[CCH];
    __shared__ float hid[8];
    int t = threadIdx.x;
    avg[t] = g_cmean[t] * (1.f / (float)NN);
    __syncthreads();
    if (t < 8) {
        float s = 0.f;
        #pragma unroll 4
        for (int c = 0; c < CCH; c++) s += w1[t * CCH + c] * avg[c];
        hid[t] = fmaxf(s, 0.f);
    }
    __syncthreads();
    float o = 0.f;
    #pragma unroll
    for (int r = 0; r < 8; r++) o += w2[t * 8 + r] * hid[r];
    g_ca[t] = 1.f / (1.f + expf(-o));
}

// ---------------- spatial stats (after CA scaling) ---------------------------
__global__ void sstat_k() {
    __shared__ float ca[CCH];
    if (threadIdx.x < CCH) ca[threadIdx.x] = g_ca[threadIdx.x];
    __syncthreads();
    int n = blockIdx.x * blockDim.x + threadIdx.x;
    if (n >= NN) return;
    float sum = 0.f, mx = -1e30f;
    const float4* hr = (const float4*)&g_Hr[n * NF];
    #pragma unroll
    for (int j = 0; j < 16; j++) {
        float4 v = hr[j];
        float a0 = v.x * ca[j*4+0], a1 = v.y * ca[j*4+1];
        float a2 = v.z * ca[j*4+2], a3 = v.w * ca[j*4+3];
        sum += a0 + a1 + a2 + a3;
        mx = fmaxf(mx, fmaxf(fmaxf(a0, a1), fmaxf(a2, a3)));
    }
    const float4* hi = (const float4*)&g_Hi[n * NF];
    #pragma unroll
    for (int j = 0; j < 16; j++) {
        float4 v = hi[j];
        float a0 = v.x * ca[64+j*4+0], a1 = v.y * ca[64+j*4+1];
        float a2 = v.z * ca[64+j*4+2], a3 = v.w * ca[64+j*4+3];
        sum += a0 + a1 + a2 + a3;
        mx = fmaxf(mx, fmaxf(fmaxf(a0, a1), fmaxf(a2, a3)));
    }
    g_smean[n] = sum * (1.f / (float)CCH);
    g_smax[n]  = mx;
}

// ---------------- spatial attention + final conv + log_softmax ---------------
__global__ void final_k(const float* __restrict__ sa_w,
                        const float* __restrict__ conv_w,
                        const float* __restrict__ conv_b,
                        float* __restrict__ out) {
    __shared__ float ca[CCH];
    __shared__ float cw[LABEL * CCH];
    __shared__ float cb[LABEL];
    __shared__ float sw[14];
    int t = threadIdx.x;
    if (t < CCH) ca[t] = g_ca[t];
    for (int idx = t; idx < LABEL * CCH; idx += blockDim.x) cw[idx] = conv_w[idx];
    if (t < LABEL) cb[t] = conv_b[t];
    if (t < 14) sw[t] = sa_w[t];
    __syncthreads();

    int n = blockIdx.x * blockDim.x + t;
    if (n >= NN) return;

    float s = 0.f;
    #pragma unroll
    for (int tap = 0; tap < 7; tap++) {
        int m = n - 3 + tap;
        if (m >= 0 && m < NN) s += sw[tap] * g_smean[m] + sw[7 + tap] * g_smax[m];
    }
    float sa = 1.f / (1.f + expf(-s));

    float acc[LABEL];
    #pragma unroll
    for (int l = 0; l < LABEL; l++) acc[l] = cb[l];

    const float* hr = &g_Hr[n * NF];
    const float* hi = &g_Hi[n * NF];
    #pragma unroll 4
    for (int c = 0; c < NF; c++) {
        float xv = hr[c] * ca[c] * sa;
        #pragma unroll
        for (int l = 0; l < LABEL; l++) acc[l] += cw[l * CCH + c] * xv;
    }
    #pragma unroll 4
    for (int c = 0; c < NF; c++) {
        float xv = hi[c] * ca[NF + c] * sa;
        #pragma unroll
        for (int l = 0; l < LABEL; l++) acc[l] += cw[l * CCH + NF + c] * xv;
    }

    float mx = acc[0];
    #pragma unroll
    for (int l = 1; l < LABEL; l++) mx = fmaxf(mx, acc[l]);
    float se = 0.f;
    #pragma unroll
    for (int l = 0; l < LABEL; l++) se += expf(acc[l] - mx);
    float lse = logf(se) + mx;
    #pragma unroll
    for (int l = 0; l < LABEL; l++) out[l * NN + n] = acc[l] - lse;
}

// ---------------- launch sequence --------------------------------------------
extern "C" void kernel_launch(void* const* d_in, const int* in_sizes, int n_in,
                              void* d_out, int out_size) {
    const float* Xr    = (const float*)d_in[0];
    const float* Xi    = (const float*)d_in[1];
    const int*   rows  = (const int*)  d_in[2];
    const int*   cols  = (const int*)  d_in[3];
    const float* vr    = (const float*)d_in[4];
    const float* vi    = (const float*)d_in[5];
    const float* w0    = (const float*)d_in[6];
    const float* b0    = (const float*)d_in[7];
    const float* w1    = (const float*)d_in[8];
    const float* b1    = (const float*)d_in[9];
    const float* w2    = (const float*)d_in[10];
    const float* b2    = (const float*)d_in[11];
    const float* caw1  = (const float*)d_in[12];
    const float* caw2  = (const float*)d_in[13];
    const float* saw   = (const float*)d_in[14];
    const float* convw = (const float*)d_in[15];
    const float* convb = (const float*)d_in[16];
    float* out = (float*)d_out;

    const dim3 gemm_grid(NTILE, 6);
    const int gather_blocks = (NN * 32 + 255) / 256;
    const int node_blocks   = (NN + 255) / 256;
    const int histws_blocks = HISTBLK + (TOTW + 255) / 256;

    // ---- CSR build + W pre-split ----
    histws_k<<<histws_blocks, 256>>>(rows, w0, w1, w2);          // launch 0
    scan_k<<<1, 1024>>>();                                       // launch 1

    // ---- layer 0 GEMM fused with scatter (interleaved blocks) ----
    gemm0_scatter_k<<<FUSEGRID, 128>>>(Xr, Xi, rows, cols, vr, vi);  // launch 2
    spmm_gather_k<<<gather_blocks, 256>>>(b0);                   // launch 3 (profiled)

    // ---- layer 1 ----
    gemm_t<NF, true><<<gemm_grid, 128>>>(nullptr, nullptr, WOFF1);
    spmm_gather_k<<<gather_blocks, 256>>>(b1);

    // ---- layer 2 ----
    gemm_t<NF, true><<<gemm_grid, 128>>>(nullptr, nullptr, WOFF2);
    spmm_gather_k<<<gather_blocks, 256>>>(b2);

    // ---- CBAM + head ----
    zero_cmean_k<<<1, 128>>>();
    chan_sum_k<<<(NN + 511) / 512, 256>>>();
    ca_k<<<1, 128>>>(caw1, caw2);
    sstat_k<<<node_blocks, 256>>>();
    final_k<<<node_blocks, 256>>>(saw, convw, convb, out);
}